// round 14
// baseline (speedup 1.0000x reference)
#include <cuda_runtime.h>
#include <cstdint>
#include <cstddef>

#define BB 16
#define MM 32
#define A_TOTAL 21824
#define NUM_FG 80
#define EPSF 1e-6f
#define BA (BB*A_TOTAL)
#define FULLM 0xFFFFFFFFu
#define GRID_BG 2048
#define GRID_FG 1364                 // 1364*256 = 349184 = BA exactly
#define TOTAL_TICKETS (GRID_BG + GRID_FG)
#define NTHREADS (GRID_BG*256)
#define NV4 (BA*20)                  // 6,983,680 float4 elements in pred_cls
#define FULL_ITERS 13                // 13*524288 = 6,815,744 <= NV4
#define TAIL (NV4 - FULL_ITERS*NTHREADS)   // 167,936

__device__ unsigned int g_posmask[BA];     // zero at load; self-cleaned each run
__device__ double g_acc[5];                // cls, reg, ctn, jsd, fgcount
__device__ unsigned g_ticket;

__constant__ int   c_lstart[5] = {0, 16384, 20480, 21504, 21760};
__constant__ int   c_feat[5]   = {128, 64, 32, 16, 8};
__constant__ float c_strf[5]   = {8.f, 16.f, 32.f, 64.f, 128.f};
__constant__ float c_invs[5]   = {0.125f, 0.0625f, 0.03125f, 0.015625f, 0.0078125f};

__device__ __forceinline__ float rcp_fast(float x) {
    float r;
    asm("rcp.approx.f32 %0, %1;" : "=f"(r) : "f"(x));
    return r;
}

// Shared finalize: every ticket-taking block calls this after its atomics.
__device__ __forceinline__ void take_ticket_and_maybe_finalize(
        float* __restrict__ out, int tidx) {
    __shared__ unsigned rank;
    if (tidx == 0) {
        __threadfence();
        rank = atomicAdd(&g_ticket, 1u);
    }
    __syncthreads();
    if (tidx == 0 && rank == (unsigned)(TOTAL_TICKETS - 1)) {
        volatile double* acc = (volatile double*)g_acc;
        double a0 = acc[0], a1 = acc[1], a2 = acc[2], a3 = acc[3], a4 = acc[4];
        float fg = (float)a4;
        float ln = 0.9f * 100.f + 0.1f * fmaxf(fg, 1.f);
        out[0] = (float)(a0 / (double)ln);
        out[1] = (float)(a1 / (double)ln);
        out[2] = (float)(a2 / (double)ln);
        out[3] = (float)(a3 / (double)ln);
        acc[0] = 0.0; acc[1] = 0.0; acc[2] = 0.0; acc[3] = 0.0; acc[4] = 0.0;
        g_ticket = 0u;
    }
}

// Background focal term for one float4 of logits:
// sum_j sigmoid(x_j)^2 * softplus(x_j); reciprocals batched via ONE rcp.
__device__ __forceinline__ float bg_term(float4 v) {
    float u0 = __expf(-v.x), u1 = __expf(-v.y);
    float u2 = __expf(-v.z), u3 = __expf(-v.w);
    float d0 = 1.f + u0, d1 = 1.f + u1, d2 = 1.f + u2, d3 = 1.f + u3;
    float p01 = d0 * d1;
    float p012 = p01 * d2;
    float P = p012 * d3;
    float inv = rcp_fast(P);
    float s23 = d2 * d3;
    float r0 = inv * (d1 * s23);
    float r1 = inv * (d0 * s23);
    float r2 = inv * (p01 * d3);
    float r3 = inv * p012;
    const float LN2 = 0.69314718056f;
    float acc;
    acc = (r0 * r0) * fmaf(__log2f(d0), LN2, v.x);
    acc = fmaf(r1 * r1, fmaf(__log2f(d1), LN2, v.y), acc);
    acc = fmaf(r2 * r2, fmaf(__log2f(d2), LN2, v.z), acc);
    acc = fmaf(r3 * r3, fmaf(__log2f(d3), LN2, v.w), acc);
    return acc;
}

// ---------------------------------------------------------------- assignment
// One warp per (b, g) = one 32-thread block (stream B). Rank-based top-9:
// each of 25 window lanes computes key = d2 bits << 32 | anchor idx (unique),
// rank_i = #{j : key_j < key_i} via 25 independent shfl broadcasts; top-9 =
// rank < 9 (selection SET identical to jax top_k; order irrelevant — mean/
// std/inside/scatter are order-invariant). Anchors are analytic (center ±
// 4*stride) so no anchor loads and no shared memory at all.
__global__ void k_assign(const float* __restrict__ gt) {
    int warp_id = blockIdx.x;
    int lane = threadIdx.x;
    int b = warp_id >> 5;   // MM == 32
    int g = warp_id & 31;

    const float* gp = gt + (size_t)(b * MM + g) * 5;
    if (gp[4] <= 0.f) return;   // invalid gt (whole warp exits together)

    float gx1 = gp[0], gy1 = gp[1], gx2 = gp[2], gy2 = gp[3];
    float gcx = 0.5f * (gx1 + gx2), gcy = 0.5f * (gy1 + gy2);
    float garea = (gx2 - gx1) * (gy2 - gy1);

    float sel_iou[5];
    int   sel_ai[5];
    bool  sel_in[5];
    float sum = 0.f;

    #pragma unroll
    for (int lvl = 0; lvl < 5; ++lvl) {
        float s = c_strf[lvl], inv = c_invs[lvl];
        int f = c_feat[lvl], start = c_lstart[lvl];
        int ix = (int)floorf(gcx * inv);
        int iy = (int)floorf(gcy * inv);
        int x0 = min(max(ix - 2, 0), f - 5);
        int y0 = min(max(iy - 2, 0), f - 5);

        unsigned long long key = ~0ull;
        float acx = 0.f, acy = 0.f;
        int ai = 0;
        if (lane < 25) {
            int cx = x0 + (lane % 5);
            int cy = y0 + (lane / 5);
            acx = ((float)cx + 0.5f) * s;
            acy = ((float)cy + 0.5f) * s;
            float dx = acx - gcx, dy = acy - gcy;
            float d2 = dx * dx + dy * dy;
            ai = start + cy * f + cx;
            key = (((unsigned long long)__float_as_uint(d2)) << 32) | (unsigned)ai;
        }

        // rank via 25 independent broadcasts (keys are unique)
        int rank = 0;
        #pragma unroll
        for (int j = 0; j < 25; ++j) {
            unsigned long long kj = __shfl_sync(FULLM, key, j);
            rank += (kj < key) ? 1 : 0;
        }
        bool sel = (lane < 25) && (rank < 9);

        float iou = 0.f;
        bool inside = false;
        if (sel) {
            float half = 4.f * s;
            float ax1 = acx - half, ay1 = acy - half;
            float ax2 = acx + half, ay2 = acy + half;
            float iw = fmaxf(fminf(ax2, gx2) - fmaxf(ax1, gx1), 0.f);
            float ih = fmaxf(fminf(ay2, gy2) - fmaxf(ay1, gy1), 0.f);
            float inter = iw * ih;
            float aarea = (2.f * half) * (2.f * half);
            float uni = fmaxf(aarea + garea - inter, EPSF);
            iou = inter / uni;
            float l = acx - gx1, tt = acy - gy1, r = gx2 - acx, bb = gy2 - acy;
            inside = fminf(fminf(l, r), fminf(tt, bb)) > 0.01f;
            sum += iou;
        }
        sel_iou[lvl] = sel ? iou : -1.f;
        sel_ai[lvl] = ai;
        sel_in[lvl] = inside;
    }

    // mean + std (ddof=1) over the 45 selected candidates
    #pragma unroll
    for (int off = 16; off; off >>= 1) sum += __shfl_xor_sync(FULLM, sum, off);
    float mean = sum * (1.f / 45.f);
    float dsum = 0.f;
    #pragma unroll
    for (int lvl = 0; lvl < 5; ++lvl) {
        if (sel_iou[lvl] >= 0.f) {
            float d = sel_iou[lvl] - mean;
            dsum += d * d;
        }
    }
    #pragma unroll
    for (int off = 16; off; off >>= 1) dsum += __shfl_xor_sync(FULLM, dsum, off);
    float thr = mean + sqrtf(fmaxf(dsum * (1.f / 44.f), 0.f));

    #pragma unroll
    for (int lvl = 0; lvl < 5; ++lvl) {
        if (sel_iou[lvl] >= thr && sel_in[lvl]) {
            atomicOr(&g_posmask[b * A_TOTAL + sel_ai[lvl]], 1u << g);
        }
    }
}

// ---------------------------------------------------------------- bg kernel
// Pure background focal stream (stream A): 13 strided float4/thread, 4
// independent loads per group (MLP=4); block-reduce; one atomic; ticket.
__global__ void k_main(const float* __restrict__ pred_cls,
                       float* __restrict__ out) {
    int gi = blockIdx.x * blockDim.x + threadIdx.x;
    float facc;
    {
        const float4* p = ((const float4*)pred_cls) + gi;
        const int stride = NTHREADS;
        float b0 = 0.f, b1 = 0.f, b2 = 0.f, b3 = 0.f;
        #pragma unroll
        for (int k = 0; k < 3; ++k) {
            float4 v0 = __ldg(p);
            float4 v1 = __ldg(p + stride);
            float4 v2 = __ldg(p + 2 * stride);
            float4 v3 = __ldg(p + 3 * stride);
            p += 4 * stride;
            b0 += bg_term(v0);
            b1 += bg_term(v1);
            b2 += bg_term(v2);
            b3 += bg_term(v3);
        }
        b0 += bg_term(__ldg(p));            // 13th element, always in range
        if (gi < TAIL)
            b1 += bg_term(__ldg(p + stride));
        facc = 0.75f * ((b0 + b1) + (b2 + b3));
    }

    #pragma unroll
    for (int off = 16; off; off >>= 1)
        facc += __shfl_xor_sync(FULLM, facc, off);
    __shared__ float sh[8];
    int w = threadIdx.x >> 5, lane = threadIdx.x & 31;
    if (lane == 0) sh[w] = facc;
    __syncthreads();
    if (threadIdx.x == 0) {
        float t = 0.f;
        #pragma unroll
        for (int k = 0; k < 8; ++k) t += sh[k];
        atomicAdd(&g_acc[0], (double)t);
    }
    take_ticket_and_maybe_finalize(out, threadIdx.x);
}

// ---------------------------------------------------------------- fg kernel
// One thread per anchor (stream B, after k_assign, concurrent with k_main).
// fg anchors: argmax-IoU gt, reg/ctn/jsd losses + focal correction
// pos(x_t)-neg(x_t); self-clean the consumed mask word; ticket.
__global__ void k_fg(const float* __restrict__ pred_cls,
                     const float* __restrict__ pred_reg,
                     const float* __restrict__ pred_ctn,
                     const float* __restrict__ anchors,
                     const float* __restrict__ gt,
                     float* __restrict__ out) {
    int idx = blockIdx.x * blockDim.x + threadIdx.x;   // 0 .. BA-1 exactly
    float lreg = 0.f, lctn = 0.f, ljsd = 0.f, lcls = 0.f, fgf = 0.f;

    unsigned mask = g_posmask[idx];
    if (mask) {
        g_posmask[idx] = 0u;
        int b = idx / A_TOTAL;
        int a = idx - b * A_TOTAL;
        fgf = 1.f;
        float4 av = ((const float4*)anchors)[a];
        float best = -1.f; int bg = 0;
        unsigned m = mask;
        while (m) {
            int gg = __ffs(m) - 1; m &= (m - 1);
            const float* gp = gt + (size_t)(b * MM + gg) * 5;
            float gx1 = gp[0], gy1 = gp[1], gx2 = gp[2], gy2 = gp[3];
            float iw = fmaxf(fminf(av.z, gx2) - fmaxf(av.x, gx1), 0.f);
            float ih = fmaxf(fminf(av.w, gy2) - fmaxf(av.y, gy1), 0.f);
            float inter = iw * ih;
            float uni = fmaxf((av.z - av.x) * (av.w - av.y) +
                              (gx2 - gx1) * (gy2 - gy1) - inter, EPSF);
            float iou = inter / uni;
            if (iou > best) { best = iou; bg = gg; }
        }
        const float* gp = gt + (size_t)(b * MM + bg) * 5;
        float gx1 = gp[0], gy1 = gp[1], gx2 = gp[2], gy2 = gp[3];
        int tgt = (int)gp[4] - 1;

        float aw = av.z - av.x, ah = av.w - av.y;
        float ax = 0.5f * (av.x + av.z), ay = 0.5f * (av.y + av.w);
        float gw = fmaxf(gx2 - gx1, EPSF), gh = fmaxf(gy2 - gy1, EPSF);
        float gcx = 0.5f * (gx1 + gx2), gcy = 0.5f * (gy1 + gy2);
        float t0 = (gcx - ax) / aw, t1 = (gcy - ay) / ah;
        float t2 = __logf(gw / aw), t3 = __logf(gh / ah);

        float tcx = ax + t0 * aw, tcy = ay + t1 * ah;
        float tw = __expf(fminf(fmaxf(t2, -4.f), 4.f)) * aw;
        float th = __expf(fminf(fmaxf(t3, -4.f), 4.f)) * ah;
        float tx1 = tcx - 0.5f * tw, ty1 = tcy - 0.5f * th;
        float tx2 = tcx + 0.5f * tw, ty2 = tcy + 0.5f * th;

        const float4* prp = (const float4*)(pred_reg + (size_t)idx * 8);
        float4 mu = prp[0], ls = prp[1];
        float pcx = ax + mu.x * aw, pcy = ay + mu.y * ah;
        float pw = __expf(fminf(fmaxf(mu.z, -4.f), 4.f)) * aw;
        float ph = __expf(fminf(fmaxf(mu.w, -4.f), 4.f)) * ah;
        float px1 = pcx - 0.5f * pw, py1 = pcy - 0.5f * ph;
        float px2 = pcx + 0.5f * pw, py2 = pcy + 0.5f * ph;

        float iw2 = fmaxf(fminf(px2, tx2) - fmaxf(px1, tx1), 0.f);
        float ih2 = fmaxf(fminf(py2, ty2) - fmaxf(py1, ty1), 0.f);
        float inter2 = iw2 * ih2;
        float a1 = (px2 - px1) * (py2 - py1);
        float a2 = (tx2 - tx1) * (ty2 - ty1);
        float uni2 = fmaxf(a1 + a2 - inter2, EPSF);
        float iou2 = inter2 / uni2;
        float ew = fmaxf(fmaxf(px2, tx2) - fminf(px1, tx1), 0.f);
        float eh = fmaxf(fmaxf(py2, ty2) - fminf(py1, ty1), 0.f);
        float enc = fmaxf(ew * eh, EPSF);
        lreg = 1.f - (iou2 - (enc - uni2) / enc);

        float cl = fmaxf(ax - tx1, EPSF), cr = fmaxf(tx2 - ax, EPSF);
        float ct = fmaxf(ay - ty1, EPSF), cb = fmaxf(ty2 - ay, EPSF);
        float ratio = (fminf(cl, cr) / fmaxf(cl, cr)) *
                      (fminf(ct, cb) / fmaxf(ct, cb));
        float ctn = sqrtf(fminf(fmaxf(ratio, EPSF), 1.f));
        float lg = pred_ctn[idx];
        lctn = fmaxf(lg, 0.f) - lg * ctn + log1pf(__expf(-fabsf(lg)));

        float mus[4] = {mu.x, mu.y, mu.z, mu.w};
        float lss[4] = {ls.x, ls.y, ls.z, ls.w};
        float ts[4]  = {t0, t1, t2, t3};
        float s = 0.f;
        #pragma unroll
        for (int k = 0; k < 4; ++k) {
            float var = __expf(2.f * lss[k]);
            float dd = mus[k] - ts[k]; dd *= dd;
            s += 0.5f * (var + dd) + (1.f + dd) * 0.5f / var - 1.f;
        }
        ljsd = 0.05f * s;

        float x = pred_cls[(size_t)idx * NUM_FG + tgt];
        float u = __expf(-fabsf(x));
        float lp = log1pf(u);
        float r = __fdividef(1.f, 1.f + u);
        float p = (x >= 0.f) ? r : u * r;
        float q = 1.f - p;
        float pos = 0.25f * q * q * (fmaxf(-x, 0.f) + lp);
        float neg = 0.75f * p * p * (fmaxf(x, 0.f) + lp);
        lcls = pos - neg;
    }

    #pragma unroll
    for (int off = 16; off; off >>= 1) {
        lcls += __shfl_xor_sync(FULLM, lcls, off);
        lreg += __shfl_xor_sync(FULLM, lreg, off);
        lctn += __shfl_xor_sync(FULLM, lctn, off);
        ljsd += __shfl_xor_sync(FULLM, ljsd, off);
        fgf  += __shfl_xor_sync(FULLM, fgf, off);
    }
    __shared__ float s_r[5][8];
    int w = threadIdx.x >> 5, lane = threadIdx.x & 31;
    if (lane == 0) {
        s_r[0][w] = lcls; s_r[1][w] = lreg; s_r[2][w] = lctn;
        s_r[3][w] = ljsd; s_r[4][w] = fgf;
    }
    __syncthreads();
    if (threadIdx.x == 0) {
        float cl = 0.f, r = 0.f, c = 0.f, j = 0.f, f = 0.f;
        #pragma unroll
        for (int k = 0; k < 8; ++k) {
            cl += s_r[0][k]; r += s_r[1][k]; c += s_r[2][k];
            j += s_r[3][k]; f += s_r[4][k];
        }
        if (f > 0.f) {
            atomicAdd(&g_acc[0], (double)cl);
            atomicAdd(&g_acc[1], (double)r);
            atomicAdd(&g_acc[2], (double)c);
            atomicAdd(&g_acc[3], (double)j);
            atomicAdd(&g_acc[4], (double)f);
        }
    }
    take_ticket_and_maybe_finalize(out, threadIdx.x);
}

// ---------------------------------------------------------------- host side
namespace {
struct Ctx {
    cudaStream_t sB = nullptr;
    cudaEvent_t evFork = nullptr, evJoin = nullptr;
    Ctx() {
        cudaStreamCreateWithFlags(&sB, cudaStreamNonBlocking);
        cudaEventCreateWithFlags(&evFork, cudaEventDisableTiming);
        cudaEventCreateWithFlags(&evJoin, cudaEventDisableTiming);
    }
};
Ctx g_ctx;   // constructed at load, before harness checkpoints
}

extern "C" void kernel_launch(void* const* d_in, const int* in_sizes, int n_in,
                              void* d_out, int out_size) {
    const float* pred_cls = (const float*)d_in[0];
    const float* pred_reg = (const float*)d_in[1];
    const float* pred_ctn = (const float*)d_in[2];
    const float* anchors  = (const float*)d_in[3];
    const float* gt       = (const float*)d_in[4];
    (void)in_sizes; (void)n_in; (void)out_size;

    // fork: stream B runs assignment -> fg losses, concurrent with bg stream
    cudaEventRecord(g_ctx.evFork, 0);
    cudaStreamWaitEvent(g_ctx.sB, g_ctx.evFork, 0);
    k_assign<<<BB * MM, 32, 0, g_ctx.sB>>>(gt);
    k_fg<<<GRID_FG, 256, 0, g_ctx.sB>>>(pred_cls, pred_reg, pred_ctn,
                                        anchors, gt, (float*)d_out);
    cudaEventRecord(g_ctx.evJoin, g_ctx.sB);

    // stream A (capture stream): the big background focal scan
    k_main<<<GRID_BG, 256>>>(pred_cls, (float*)d_out);

    // join so the graph's leaf includes both streams
    cudaStreamWaitEvent(0, g_ctx.evJoin, 0);
}

// round 15
// speedup vs baseline: 1.0609x; 1.0609x over previous
#include <cuda_runtime.h>
#include <cstdint>
#include <cstddef>

#define BB 16
#define MM 32
#define A_TOTAL 21824
#define NUM_FG 80
#define EPSF 1e-6f
#define BA (BB*A_TOTAL)
#define FULLM 0xFFFFFFFFu
#define GRID_BG 2048
#define GRID_FG 32                   // compact fg kernel: 32 blocks
#define TOTAL_TICKETS (GRID_BG + GRID_FG)
#define NTHREADS (GRID_BG*256)
#define NV4 (BA*20)                  // 6,983,680 float4 elements in pred_cls
#define FULL_ITERS 13                // 13*524288 = 6,815,744 <= NV4
#define TAIL (NV4 - FULL_ITERS*NTHREADS)   // 167,936
#define FGLIST_CAP 24576             // >= 512 gts * 45 candidates worst case

__device__ unsigned int g_posmask[BA];   // zero at load; k_fg cleans touched words
__device__ int g_fglist[FGLIST_CAP];     // compact list of touched anchor idxs
__device__ int g_fgcnt;                  // list length; reset by finalizer
__device__ double g_acc[5];              // cls, reg, ctn, jsd, fgcount
__device__ unsigned g_ticket;

__constant__ int   c_feat[5]   = {128, 64, 32, 16, 8};
__constant__ int   c_lstart[5] = {0, 16384, 20480, 21504, 21760};
__constant__ float c_strf[5]   = {8.f, 16.f, 32.f, 64.f, 128.f};
__constant__ float c_invs[5]   = {0.125f, 0.0625f, 0.03125f, 0.015625f, 0.0078125f};

__device__ __forceinline__ float rcp_fast(float x) {
    float r;
    asm("rcp.approx.f32 %0, %1;" : "=f"(r) : "f"(x));
    return r;
}

// Shared finalize: every ticket-taking block calls this after its atomics.
__device__ __forceinline__ void take_ticket_and_maybe_finalize(
        float* __restrict__ out, int tidx) {
    __shared__ unsigned rank;
    if (tidx == 0) {
        __threadfence();
        rank = atomicAdd(&g_ticket, 1u);
    }
    __syncthreads();
    if (tidx == 0 && rank == (unsigned)(TOTAL_TICKETS - 1)) {
        volatile double* acc = (volatile double*)g_acc;
        double a0 = acc[0], a1 = acc[1], a2 = acc[2], a3 = acc[3], a4 = acc[4];
        float fg = (float)a4;
        float ln = 0.9f * 100.f + 0.1f * fmaxf(fg, 1.f);
        out[0] = (float)(a0 / (double)ln);
        out[1] = (float)(a1 / (double)ln);
        out[2] = (float)(a2 / (double)ln);
        out[3] = (float)(a3 / (double)ln);
        acc[0] = 0.0; acc[1] = 0.0; acc[2] = 0.0; acc[3] = 0.0; acc[4] = 0.0;
        g_fgcnt = 0;
        g_ticket = 0u;
    }
}

// Background focal term for one float4 of logits:
// sum_j sigmoid(x_j)^2 * softplus(x_j); reciprocals batched via ONE rcp.
__device__ __forceinline__ float bg_term(float4 v) {
    float u0 = __expf(-v.x), u1 = __expf(-v.y);
    float u2 = __expf(-v.z), u3 = __expf(-v.w);
    float d0 = 1.f + u0, d1 = 1.f + u1, d2 = 1.f + u2, d3 = 1.f + u3;
    float p01 = d0 * d1;
    float p012 = p01 * d2;
    float P = p012 * d3;
    float inv = rcp_fast(P);
    float s23 = d2 * d3;
    float r0 = inv * (d1 * s23);
    float r1 = inv * (d0 * s23);
    float r2 = inv * (p01 * d3);
    float r3 = inv * p012;
    const float LN2 = 0.69314718056f;
    float acc;
    acc = (r0 * r0) * fmaf(__log2f(d0), LN2, v.x);
    acc = fmaf(r1 * r1, fmaf(__log2f(d1), LN2, v.y), acc);
    acc = fmaf(r2 * r2, fmaf(__log2f(d2), LN2, v.z), acc);
    acc = fmaf(r3 * r3, fmaf(__log2f(d3), LN2, v.w), acc);
    return acc;
}

// ---------------------------------------------------------------- assignment
// One warp per (b, g) = one 32-thread block (stream B). Rank-based top-9:
// each of 25 window lanes computes key = d2 bits << 32 | anchor idx (unique),
// rank_i = #{j : key_j < key_i} via 25 independent shfl broadcasts; top-9 =
// rank < 9 (selection SET identical to jax top_k; order irrelevant — mean/
// std/inside/scatter are order-invariant). Anchors are analytic so no loads.
// NEW: the atomicOr return value elects the FIRST writer of each anchor word,
// which appends the anchor's flat index to g_fglist (compact fg set).
__global__ void k_assign(const float* __restrict__ gt) {
    int warp_id = blockIdx.x;
    int lane = threadIdx.x;
    int b = warp_id >> 5;   // MM == 32
    int g = warp_id & 31;

    const float* gp = gt + (size_t)(b * MM + g) * 5;
    if (gp[4] <= 0.f) return;   // invalid gt (whole warp exits together)

    float gx1 = gp[0], gy1 = gp[1], gx2 = gp[2], gy2 = gp[3];
    float gcx = 0.5f * (gx1 + gx2), gcy = 0.5f * (gy1 + gy2);
    float garea = (gx2 - gx1) * (gy2 - gy1);

    float sel_iou[5];
    int   sel_ai[5];
    bool  sel_in[5];
    float sum = 0.f;

    #pragma unroll
    for (int lvl = 0; lvl < 5; ++lvl) {
        float s = c_strf[lvl], inv = c_invs[lvl];
        int f = c_feat[lvl], start = c_lstart[lvl];
        int ix = (int)floorf(gcx * inv);
        int iy = (int)floorf(gcy * inv);
        int x0 = min(max(ix - 2, 0), f - 5);
        int y0 = min(max(iy - 2, 0), f - 5);

        unsigned long long key = ~0ull;
        float acx = 0.f, acy = 0.f;
        int ai = 0;
        if (lane < 25) {
            int cx = x0 + (lane % 5);
            int cy = y0 + (lane / 5);
            acx = ((float)cx + 0.5f) * s;
            acy = ((float)cy + 0.5f) * s;
            float dx = acx - gcx, dy = acy - gcy;
            float d2 = dx * dx + dy * dy;
            ai = start + cy * f + cx;
            key = (((unsigned long long)__float_as_uint(d2)) << 32) | (unsigned)ai;
        }

        // rank via 25 independent broadcasts (keys are unique)
        int rank = 0;
        #pragma unroll
        for (int j = 0; j < 25; ++j) {
            unsigned long long kj = __shfl_sync(FULLM, key, j);
            rank += (kj < key) ? 1 : 0;
        }
        bool sel = (lane < 25) && (rank < 9);

        float iou = 0.f;
        bool inside = false;
        if (sel) {
            float half = 4.f * s;
            float ax1 = acx - half, ay1 = acy - half;
            float ax2 = acx + half, ay2 = acy + half;
            float iw = fmaxf(fminf(ax2, gx2) - fmaxf(ax1, gx1), 0.f);
            float ih = fmaxf(fminf(ay2, gy2) - fmaxf(ay1, gy1), 0.f);
            float inter = iw * ih;
            float aarea = (2.f * half) * (2.f * half);
            float uni = fmaxf(aarea + garea - inter, EPSF);
            iou = inter / uni;
            float l = acx - gx1, tt = acy - gy1, r = gx2 - acx, bb = gy2 - acy;
            inside = fminf(fminf(l, r), fminf(tt, bb)) > 0.01f;
            sum += iou;
        }
        sel_iou[lvl] = sel ? iou : -1.f;
        sel_ai[lvl] = ai;
        sel_in[lvl] = inside;
    }

    // mean + std (ddof=1) over the 45 selected candidates
    #pragma unroll
    for (int off = 16; off; off >>= 1) sum += __shfl_xor_sync(FULLM, sum, off);
    float mean = sum * (1.f / 45.f);
    float dsum = 0.f;
    #pragma unroll
    for (int lvl = 0; lvl < 5; ++lvl) {
        if (sel_iou[lvl] >= 0.f) {
            float d = sel_iou[lvl] - mean;
            dsum += d * d;
        }
    }
    #pragma unroll
    for (int off = 16; off; off >>= 1) dsum += __shfl_xor_sync(FULLM, dsum, off);
    float thr = mean + sqrtf(fmaxf(dsum * (1.f / 44.f), 0.f));

    #pragma unroll
    for (int lvl = 0; lvl < 5; ++lvl) {
        if (sel_iou[lvl] >= thr && sel_in[lvl]) {
            int flat = b * A_TOTAL + sel_ai[lvl];
            unsigned old = atomicOr(&g_posmask[flat], 1u << g);
            if (old == 0u) {
                int slot = atomicAdd(&g_fgcnt, 1);
                if (slot < FGLIST_CAP) g_fglist[slot] = flat;
            }
        }
    }
}

// ---------------------------------------------------------------- bg kernel
// Pure background focal stream (stream A): 13 strided float4/thread, 4
// independent loads per group (MLP=4); block-reduce; one atomic; ticket.
__global__ void k_main(const float* __restrict__ pred_cls,
                       float* __restrict__ out) {
    int gi = blockIdx.x * blockDim.x + threadIdx.x;
    float facc;
    {
        const float4* p = ((const float4*)pred_cls) + gi;
        const int stride = NTHREADS;
        float b0 = 0.f, b1 = 0.f, b2 = 0.f, b3 = 0.f;
        #pragma unroll
        for (int k = 0; k < 3; ++k) {
            float4 v0 = __ldg(p);
            float4 v1 = __ldg(p + stride);
            float4 v2 = __ldg(p + 2 * stride);
            float4 v3 = __ldg(p + 3 * stride);
            p += 4 * stride;
            b0 += bg_term(v0);
            b1 += bg_term(v1);
            b2 += bg_term(v2);
            b3 += bg_term(v3);
        }
        b0 += bg_term(__ldg(p));            // 13th element, always in range
        if (gi < TAIL)
            b1 += bg_term(__ldg(p + stride));
        facc = 0.75f * ((b0 + b1) + (b2 + b3));
    }

    #pragma unroll
    for (int off = 16; off; off >>= 1)
        facc += __shfl_xor_sync(FULLM, facc, off);
    __shared__ float sh[8];
    int w = threadIdx.x >> 5, lane = threadIdx.x & 31;
    if (lane == 0) sh[w] = facc;
    __syncthreads();
    if (threadIdx.x == 0) {
        float t = 0.f;
        #pragma unroll
        for (int k = 0; k < 8; ++k) t += sh[k];
        atomicAdd(&g_acc[0], (double)t);
    }
    take_ticket_and_maybe_finalize(out, threadIdx.x);
}

// ---------------------------------------------------------------- fg kernel
// Compact: 32 blocks grid-stride over the g_fglist entries only (~1-3K fg
// anchors). Each entry: read+zero its posmask word, argmax-IoU gt, losses +
// focal correction pos(x_t)-neg(x_t). Runs on stream B under k_main.
__global__ void k_fg(const float* __restrict__ pred_cls,
                     const float* __restrict__ pred_reg,
                     const float* __restrict__ pred_ctn,
                     const float* __restrict__ anchors,
                     const float* __restrict__ gt,
                     float* __restrict__ out) {
    int cnt = min(g_fgcnt, FGLIST_CAP);
    float lreg = 0.f, lctn = 0.f, ljsd = 0.f, lcls = 0.f, fgf = 0.f;

    for (int i = blockIdx.x * blockDim.x + threadIdx.x; i < cnt;
         i += GRID_FG * 256) {
        int idx = g_fglist[i];
        unsigned mask = g_posmask[idx];
        g_posmask[idx] = 0u;
        if (!mask) continue;
        int b = idx / A_TOTAL;
        int a = idx - b * A_TOTAL;
        fgf += 1.f;
        float4 av = ((const float4*)anchors)[a];
        float best = -1.f; int bg = 0;
        unsigned m = mask;
        while (m) {
            int gg = __ffs(m) - 1; m &= (m - 1);
            const float* gp = gt + (size_t)(b * MM + gg) * 5;
            float gx1 = gp[0], gy1 = gp[1], gx2 = gp[2], gy2 = gp[3];
            float iw = fmaxf(fminf(av.z, gx2) - fmaxf(av.x, gx1), 0.f);
            float ih = fmaxf(fminf(av.w, gy2) - fmaxf(av.y, gy1), 0.f);
            float inter = iw * ih;
            float uni = fmaxf((av.z - av.x) * (av.w - av.y) +
                              (gx2 - gx1) * (gy2 - gy1) - inter, EPSF);
            float iou = inter / uni;
            if (iou > best) { best = iou; bg = gg; }
        }
        const float* gp = gt + (size_t)(b * MM + bg) * 5;
        float gx1 = gp[0], gy1 = gp[1], gx2 = gp[2], gy2 = gp[3];
        int tgt = (int)gp[4] - 1;

        float aw = av.z - av.x, ah = av.w - av.y;
        float ax = 0.5f * (av.x + av.z), ay = 0.5f * (av.y + av.w);
        float gw = fmaxf(gx2 - gx1, EPSF), gh = fmaxf(gy2 - gy1, EPSF);
        float gcx = 0.5f * (gx1 + gx2), gcy = 0.5f * (gy1 + gy2);
        float t0 = (gcx - ax) / aw, t1 = (gcy - ay) / ah;
        float t2 = __logf(gw / aw), t3 = __logf(gh / ah);

        float tcx = ax + t0 * aw, tcy = ay + t1 * ah;
        float tw = __expf(fminf(fmaxf(t2, -4.f), 4.f)) * aw;
        float th = __expf(fminf(fmaxf(t3, -4.f), 4.f)) * ah;
        float tx1 = tcx - 0.5f * tw, ty1 = tcy - 0.5f * th;
        float tx2 = tcx + 0.5f * tw, ty2 = tcy + 0.5f * th;

        const float4* prp = (const float4*)(pred_reg + (size_t)idx * 8);
        float4 mu = prp[0], ls = prp[1];
        float pcx = ax + mu.x * aw, pcy = ay + mu.y * ah;
        float pw = __expf(fminf(fmaxf(mu.z, -4.f), 4.f)) * aw;
        float ph = __expf(fminf(fmaxf(mu.w, -4.f), 4.f)) * ah;
        float px1 = pcx - 0.5f * pw, py1 = pcy - 0.5f * ph;
        float px2 = pcx + 0.5f * pw, py2 = pcy + 0.5f * ph;

        float iw2 = fmaxf(fminf(px2, tx2) - fmaxf(px1, tx1), 0.f);
        float ih2 = fmaxf(fminf(py2, ty2) - fmaxf(py1, ty1), 0.f);
        float inter2 = iw2 * ih2;
        float a1 = (px2 - px1) * (py2 - py1);
        float a2 = (tx2 - tx1) * (ty2 - ty1);
        float uni2 = fmaxf(a1 + a2 - inter2, EPSF);
        float iou2 = inter2 / uni2;
        float ew = fmaxf(fmaxf(px2, tx2) - fminf(px1, tx1), 0.f);
        float eh = fmaxf(fmaxf(py2, ty2) - fminf(py1, ty1), 0.f);
        float enc = fmaxf(ew * eh, EPSF);
        lreg += 1.f - (iou2 - (enc - uni2) / enc);

        float cl = fmaxf(ax - tx1, EPSF), cr = fmaxf(tx2 - ax, EPSF);
        float ct = fmaxf(ay - ty1, EPSF), cb = fmaxf(ty2 - ay, EPSF);
        float ratio = (fminf(cl, cr) / fmaxf(cl, cr)) *
                      (fminf(ct, cb) / fmaxf(ct, cb));
        float ctn = sqrtf(fminf(fmaxf(ratio, EPSF), 1.f));
        float lg = pred_ctn[idx];
        lctn += fmaxf(lg, 0.f) - lg * ctn + log1pf(__expf(-fabsf(lg)));

        float mus[4] = {mu.x, mu.y, mu.z, mu.w};
        float lss[4] = {ls.x, ls.y, ls.z, ls.w};
        float ts[4]  = {t0, t1, t2, t3};
        float s = 0.f;
        #pragma unroll
        for (int k = 0; k < 4; ++k) {
            float var = __expf(2.f * lss[k]);
            float dd = mus[k] - ts[k]; dd *= dd;
            s += 0.5f * (var + dd) + (1.f + dd) * 0.5f / var - 1.f;
        }
        ljsd += 0.05f * s;

        float x = pred_cls[(size_t)idx * NUM_FG + tgt];
        float u = __expf(-fabsf(x));
        float lp = log1pf(u);
        float r = __fdividef(1.f, 1.f + u);
        float p = (x >= 0.f) ? r : u * r;
        float q = 1.f - p;
        float pos = 0.25f * q * q * (fmaxf(-x, 0.f) + lp);
        float neg = 0.75f * p * p * (fmaxf(x, 0.f) + lp);
        lcls += pos - neg;
    }

    #pragma unroll
    for (int off = 16; off; off >>= 1) {
        lcls += __shfl_xor_sync(FULLM, lcls, off);
        lreg += __shfl_xor_sync(FULLM, lreg, off);
        lctn += __shfl_xor_sync(FULLM, lctn, off);
        ljsd += __shfl_xor_sync(FULLM, ljsd, off);
        fgf  += __shfl_xor_sync(FULLM, fgf, off);
    }
    __shared__ float s_r[5][8];
    int w = threadIdx.x >> 5, lane = threadIdx.x & 31;
    if (lane == 0) {
        s_r[0][w] = lcls; s_r[1][w] = lreg; s_r[2][w] = lctn;
        s_r[3][w] = ljsd; s_r[4][w] = fgf;
    }
    __syncthreads();
    if (threadIdx.x == 0) {
        float cl = 0.f, r = 0.f, c = 0.f, j = 0.f, f = 0.f;
        #pragma unroll
        for (int k = 0; k < 8; ++k) {
            cl += s_r[0][k]; r += s_r[1][k]; c += s_r[2][k];
            j += s_r[3][k]; f += s_r[4][k];
        }
        if (f > 0.f) {
            atomicAdd(&g_acc[0], (double)cl);
            atomicAdd(&g_acc[1], (double)r);
            atomicAdd(&g_acc[2], (double)c);
            atomicAdd(&g_acc[3], (double)j);
            atomicAdd(&g_acc[4], (double)f);
        }
    }
    take_ticket_and_maybe_finalize(out, threadIdx.x);
}

// ---------------------------------------------------------------- host side
namespace {
struct Ctx {
    cudaStream_t sB = nullptr;
    cudaEvent_t evFork = nullptr, evJoin = nullptr;
    Ctx() {
        cudaStreamCreateWithFlags(&sB, cudaStreamNonBlocking);
        cudaEventCreateWithFlags(&evFork, cudaEventDisableTiming);
        cudaEventCreateWithFlags(&evJoin, cudaEventDisableTiming);
    }
};
Ctx g_ctx;   // constructed at load, before harness checkpoints
}

extern "C" void kernel_launch(void* const* d_in, const int* in_sizes, int n_in,
                              void* d_out, int out_size) {
    const float* pred_cls = (const float*)d_in[0];
    const float* pred_reg = (const float*)d_in[1];
    const float* pred_ctn = (const float*)d_in[2];
    const float* anchors  = (const float*)d_in[3];
    const float* gt       = (const float*)d_in[4];
    (void)in_sizes; (void)n_in; (void)out_size;

    // fork: stream B runs assignment -> compact fg losses, under k_main
    cudaEventRecord(g_ctx.evFork, 0);
    cudaStreamWaitEvent(g_ctx.sB, g_ctx.evFork, 0);
    k_assign<<<BB * MM, 32, 0, g_ctx.sB>>>(gt);
    k_fg<<<GRID_FG, 256, 0, g_ctx.sB>>>(pred_cls, pred_reg, pred_ctn,
                                        anchors, gt, (float*)d_out);
    cudaEventRecord(g_ctx.evJoin, g_ctx.sB);

    // stream A (capture stream): the big background focal scan
    k_main<<<GRID_BG, 256>>>(pred_cls, (float*)d_out);

    // join so the graph's leaf includes both streams
    cudaStreamWaitEvent(0, g_ctx.evJoin, 0);
}